// round 10
// baseline (speedup 1.0000x reference)
#include <cuda_runtime.h>
#include <cooperative_groups.h>
#include <cstdint>

namespace cg = cooperative_groups;

// ---------------- problem dims ----------------
#define BB 512
#define TT 64
#define HH 256     // hidden / obs dim
#define AA 6       // action dim
#define RR 256     // recurrent dim
#define KG 768     // 3*RR gate dim
#define LL 1024    // latent dim
#define NCTA 128   // CTAs (64 clusters of 2); each cluster owns 8 rows, each CTA owns 4

// output layout: [deter | stoch | logits]
#define DET_OFF 0
#define ST_OFF  (BB * TT * RR)
#define LG_OFF  (BB * TT * RR + BB * TT * LL)

// ---------------- device scratch ----------------
__device__ __align__(16) float g_WcT[LL * KG];     // [c][k] fused stoch weights
__device__ __align__(16) float g_WcaT[AA * KG];    // [j][k] fused action weights
__device__ __align__(16) float g_bc[KG];           // b_ih + W_ih @ b_in
__device__ __align__(16) float g_WhhT[RR * KG];    // [j][k]
__device__ __align__(16) float g_WphT[RR * LL];    // [j][l]
__device__ __align__(16) float g_WpoT[HH * LL];    // [k][n]

// ---------------- packed fp32 helpers (FFMA2 path) ----------------
__device__ __forceinline__ void ffma2(float2& d, const float2 a, const float2 b) {
    asm("fma.rn.f32x2 %0, %1, %2, %0;"
        : "+l"(reinterpret_cast<unsigned long long&>(d))
        : "l"(reinterpret_cast<const unsigned long long&>(a)),
          "l"(reinterpret_cast<const unsigned long long&>(b)));
}

// ---------------- prep 1: fuse W_ih @ [W_in | b_in] ----------------
__global__ void prep_fuse(const float* __restrict__ W_in, const float* __restrict__ b_in,
                          const float* __restrict__ W_ih, const float* __restrict__ b_ih) {
    int idx = blockIdx.x * blockDim.x + threadIdx.x;
    if (idx >= KG * 1031) return;
    int k = idx / 1031;
    int c = idx % 1031;
    float acc = 0.f;
    if (c < 1030) {
        for (int h = 0; h < HH; ++h)
            acc = fmaf(W_ih[k * HH + h], W_in[h * 1030 + c], acc);
        if (c < LL) g_WcT[c * KG + k] = acc;
        else        g_WcaT[(c - LL) * KG + k] = acc;
    } else {
        for (int h = 0; h < HH; ++h)
            acc = fmaf(W_ih[k * HH + h], b_in[h], acc);
        g_bc[k] = acc + b_ih[k];
    }
}

// ---------------- prep 2: transposes ----------------
__global__ void prep_transpose(const float* __restrict__ W_hh, const float* __restrict__ W_post) {
    int idx = blockIdx.x * blockDim.x + threadIdx.x;
    const int T1 = KG * RR;
    const int T2 = LL * (RR + HH);
    if (idx < T1) {
        int k = idx / RR, j = idx % RR;
        g_WhhT[j * KG + k] = W_hh[idx];
    } else if (idx < T1 + T2) {
        int e = idx - T1;
        int l = e / (RR + HH), m = e % (RR + HH);
        float v = W_post[e];
        if (m < RR) g_WphT[m * LL + l] = v;
        else        g_WpoT[(m - RR) * LL + l] = v;
    }
}

// ---------------- cluster-2 persistent scan with folded obs-GEMV ----------------
#define OFF_GI     0
#define OFF_GH8    3072
#define OFF_GHR    9216
#define OFF_DET8   12288
#define OFF_DETOWN 16384
#define OFF_LG8    18432
#define OFF_LGR    26624
#define OFF_OBS8   30720
#define SMEM_FLOATS 32768

__global__ void __launch_bounds__(512, 1) __cluster_dims__(2, 1, 1)
scan_kernel(const float* __restrict__ obs,
            const float* __restrict__ action,
            const unsigned int* __restrict__ first,
            const float* __restrict__ gumbel,       // [T][B][1024]
            const float* __restrict__ b_hh,
            const float* __restrict__ b_post,
            float* __restrict__ out) {

    extern __shared__ float smem[];
    float* s_gi     = smem + OFF_GI;
    float* s_gh8    = smem + OFF_GH8;
    float* s_ghr    = smem + OFF_GHR;
    float* s_det8   = smem + OFF_DET8;
    float* s_detown = smem + OFF_DETOWN;
    float* s_lg8    = smem + OFF_LG8;
    float* s_lgr    = smem + OFF_LGR;
    float* s_obs8   = smem + OFF_OBS8;
    __shared__ int   s_idx[4][32];
    __shared__ float s_act[4][AA];
    __shared__ int   s_reset[8];     // pair-global rows, first[t]

    cg::cluster_group cluster = cg::this_cluster();
    const int rank = (int)cluster.block_rank();
    float* p_ghr  = (float*)cluster.map_shared_rank(s_ghr,  rank ^ 1);
    float* p_det8 = (float*)cluster.map_shared_rank(s_det8, rank ^ 1);
    float* p_lgr  = (float*)cluster.map_shared_rank(s_lgr,  rank ^ 1);

    const int tid = threadIdx.x;
    const int jh  = tid >> 8;        // intra-CTA jj-half
    const int lk  = tid & 255;
    const int pair  = blockIdx.x >> 1;
    const int prow0 = pair * 8;
    const int orow0 = prow0 + rank * 4;      // own rows base
    const int Jbase = rank * 128;            // this CTA's j/k slice
    int cur = 0;

    for (int t = 0; t < TT; ++t) {
        // ---- flags (all 8 rows) + action (own rows) ----
        if (tid < 8) {
            unsigned f = first[(prow0 + tid) * TT + t];
            s_reset[tid] = (t == 0) || (f != 0u);
        }
        if (tid >= 32 && tid < 32 + 4 * AA) {
            int e = tid - 32;
            s_act[e / AA][e % AA] = action[((size_t)(orow0 + e / AA) * TT + t) * AA + (e % AA)];
        }
        __syncthreads();

        // ---- zero carries on reset + preload obs k-slice for all 8 rows ----
        #pragma unroll
        for (int k = 0; k < 2; ++k) {
            int idx = tid + k * 512;       // 1024 items: det8 slice
            int jj = idx >> 3, g = idx & 7;
            if (s_reset[g])
                *(float2*)&s_det8[cur * 2048 + jj * 16 + 2 * g] = make_float2(0.f, 0.f);
        }
        #pragma unroll
        for (int k = 0; k < 2; ++k) {
            int idx = tid + k * 512;       // 1024 items: detown
            int r = idx >> 8, u = idx & 255;
            if (s_reset[rank * 4 + r])
                s_detown[cur * 1024 + r * 256 + u] = 0.f;
        }
        #pragma unroll
        for (int k2 = 0; k2 < 2; ++k2) {   // obs slice: 8 rows x 128 k, packed {v,v} x 8 rows
            int idx = tid + k2 * 512;
            int kk = idx & 127;
            int g  = idx >> 7;
            float v = obs[((size_t)(prow0 + g) * TT + t) * HH + Jbase + kk];
            *(float2*)&s_obs8[kk * 16 + 2 * g] = make_float2(v, v);
        }
        __syncthreads();

        // ---- phase 1: gh partial (lk<192) || gi gather on idle threads (lk>=192) ----
        float2 gh[8][2];
        if (lk < 192) {
            const int q4 = lk * 4;
            if (rank == 0 && jh == 0) {
                float4 bh = *(const float4*)&b_hh[q4];
                #pragma unroll
                for (int g = 0; g < 8; ++g) {
                    gh[g][0] = make_float2(bh.x, bh.y);
                    gh[g][1] = make_float2(bh.z, bh.w);
                }
            } else {
                #pragma unroll
                for (int g = 0; g < 8; ++g) {
                    gh[g][0] = make_float2(0.f, 0.f);
                    gh[g][1] = make_float2(0.f, 0.f);
                }
            }
            const float4* wp  = (const float4*)&g_WhhT[(size_t)(Jbase + jh * 64) * KG + q4];
            const size_t  WS  = KG / 4;
            const float4* db4 = (const float4*)(s_det8 + cur * 2048 + (jh * 64) * 16);
            float4 wb8[8];
            #pragma unroll
            for (int p = 0; p < 8; ++p) wb8[p] = wp[(size_t)p * WS];
            #pragma unroll 1
            for (int base = 0; base < 64; base += 8) {
                #pragma unroll
                for (int p = 0; p < 8; ++p) {
                    float4 w = wb8[p];
                    int nj = base + 8 + p; nj = (nj < 64) ? nj : 63;
                    wb8[p] = wp[(size_t)nj * WS];
                    const float4* dq = db4 + (size_t)(base + p) * 4;
                    float4 dA = dq[0], dB = dq[1], dC = dq[2], dD = dq[3];
                    float2 wl = make_float2(w.x, w.y), wh2 = make_float2(w.z, w.w);
                    float2 dp[8] = { make_float2(dA.x, dA.y), make_float2(dA.z, dA.w),
                                     make_float2(dB.x, dB.y), make_float2(dB.z, dB.w),
                                     make_float2(dC.x, dC.y), make_float2(dC.z, dC.w),
                                     make_float2(dD.x, dD.y), make_float2(dD.z, dD.w) };
                    #pragma unroll
                    for (int g = 0; g < 8; ++g) {
                        ffma2(gh[g][0], dp[g], wl);
                        ffma2(gh[g][1], dp[g], wh2);
                    }
                }
            }
            if (jh == 0) {
                #pragma unroll
                for (int g = 0; g < 8; ++g)
                    *(float4*)&s_gh8[g * KG + q4] =
                        make_float4(gh[g][0].x, gh[g][0].y, gh[g][1].x, gh[g][1].y);
            }
        } else {
            // gi for own rows: 128 threads x 6 items = 768 quads
            const int w = jh * 64 + (lk - 192);       // 0..127
            #pragma unroll 1
            for (int it = 0; it < 6; ++it) {
                int item = w * 6 + it;
                int r = item / 192;
                int q = (item % 192) * 4;
                float4 a4 = *(const float4*)&g_bc[q];
                #pragma unroll
                for (int j = 0; j < AA; ++j) {
                    float av = s_act[r][j];
                    float4 wv = *(const float4*)&g_WcaT[j * KG + q];
                    a4.x = fmaf(av, wv.x, a4.x); a4.y = fmaf(av, wv.y, a4.y);
                    a4.z = fmaf(av, wv.z, a4.z); a4.w = fmaf(av, wv.w, a4.w);
                }
                if (!s_reset[rank * 4 + r]) {
                    #pragma unroll 8
                    for (int g = 0; g < 32; ++g) {
                        int c = (g << 5) + s_idx[r][g];
                        float4 wv = *(const float4*)&g_WcT[c * KG + q];
                        a4.x += wv.x; a4.y += wv.y; a4.z += wv.z; a4.w += wv.w;
                    }
                }
                *(float4*)&s_gi[r * KG + q] = a4;
            }
        }
        __syncthreads();
        if (jh == 1 && lk < 192) {   // combine halves; push peer rows to peer's s_ghr
            const int q4 = lk * 4;
            const int pb = (rank ^ 1) * 4;
            #pragma unroll
            for (int g = 0; g < 8; ++g) {
                float4 p = *(const float4*)&s_gh8[g * KG + q4];
                float4 c = make_float4(p.x + gh[g][0].x, p.y + gh[g][0].y,
                                       p.z + gh[g][1].x, p.w + gh[g][1].y);
                *(float4*)&s_gh8[g * KG + q4] = c;
                if (g >= pb && g < pb + 4)
                    *(float4*)&p_ghr[(g - pb) * KG + q4] = c;
            }
        }
        cluster.sync();   // CS1: gh partials exchanged

        // ---- GRU for own rows + det distribution ----
        {
            const int u = lk;
            #pragma unroll
            for (int ii = 0; ii < 2; ++ii) {
                int i = jh * 2 + ii;          // own-local row
                int g = rank * 4 + i;         // pair-global row
                float ir = s_gi[i * KG + u];
                float hr = s_gh8[g * KG + u]       + s_ghr[i * KG + u];
                float iz = s_gi[i * KG + u + 256];
                float hz = s_gh8[g * KG + u + 256] + s_ghr[i * KG + u + 256];
                float in_ = s_gi[i * KG + u + 512];
                float hn = s_gh8[g * KG + u + 512] + s_ghr[i * KG + u + 512];
                float rg = 1.f / (1.f + expf(-(ir + hr)));
                float z  = 1.f / (1.f + expf(-(iz + hz)));
                float n  = tanhf(fmaf(rg, hn, in_));
                float dp = s_detown[cur * 1024 + i * 256 + u];
                float h  = (1.f - z) * n + z * dp;
                s_detown[(cur ^ 1) * 1024 + i * 256 + u] = h;
                float2 hh = make_float2(h, h);
                int jloc = u & 127;
                if ((u >> 7) == rank)
                    *(float2*)&s_det8[(cur ^ 1) * 2048 + jloc * 16 + 2 * g] = hh;
                else
                    *(float2*)&p_det8[(cur ^ 1) * 2048 + jloc * 16 + 2 * g] = hh;
                out[DET_OFF + ((size_t)(orow0 + i) * TT + t) * RR + u] = h;
            }
        }
        cluster.sync();   // CS2: new det slices exchanged

        // ---- phase 2: (h·Wph + obs·Wpo) partial over my j/k-slice, dual prefetch ----
        float2 acc[8][2];
        {
            const int q4 = lk * 4;
            #pragma unroll
            for (int g = 0; g < 8; ++g) {
                acc[g][0] = make_float2(0.f, 0.f);
                acc[g][1] = make_float2(0.f, 0.f);
            }
            const float4* wph = (const float4*)&g_WphT[(size_t)(Jbase + jh * 64) * LL + q4];
            const float4* wpo = (const float4*)&g_WpoT[(size_t)(Jbase + jh * 64) * LL + q4];
            const size_t  WS  = LL / 4;
            const float4* db4 = (const float4*)(s_det8 + (cur ^ 1) * 2048 + (jh * 64) * 16);
            const float4* ob4 = (const float4*)(s_obs8 + (jh * 64) * 16);
            float4 wb1[4], wb2[4];
            #pragma unroll
            for (int p = 0; p < 4; ++p) {
                wb1[p] = wph[(size_t)p * WS];
                wb2[p] = wpo[(size_t)p * WS];
            }
            #pragma unroll 1
            for (int base = 0; base < 64; base += 4) {
                #pragma unroll
                for (int p = 0; p < 4; ++p) {
                    float4 w1 = wb1[p], w2 = wb2[p];
                    int nj = base + 4 + p; nj = (nj < 64) ? nj : 63;
                    wb1[p] = wph[(size_t)nj * WS];
                    wb2[p] = wpo[(size_t)nj * WS];
                    const float4* dq = db4 + (size_t)(base + p) * 4;
                    const float4* oq = ob4 + (size_t)(base + p) * 4;
                    float4 dA = dq[0], dB = dq[1], dC = dq[2], dD = dq[3];
                    float4 oA = oq[0], oB = oq[1], oC = oq[2], oD = oq[3];
                    float2 w1l = make_float2(w1.x, w1.y), w1h = make_float2(w1.z, w1.w);
                    float2 w2l = make_float2(w2.x, w2.y), w2h = make_float2(w2.z, w2.w);
                    float2 dp[8] = { make_float2(dA.x, dA.y), make_float2(dA.z, dA.w),
                                     make_float2(dB.x, dB.y), make_float2(dB.z, dB.w),
                                     make_float2(dC.x, dC.y), make_float2(dC.z, dC.w),
                                     make_float2(dD.x, dD.y), make_float2(dD.z, dD.w) };
                    float2 op[8] = { make_float2(oA.x, oA.y), make_float2(oA.z, oA.w),
                                     make_float2(oB.x, oB.y), make_float2(oB.z, oB.w),
                                     make_float2(oC.x, oC.y), make_float2(oC.z, oC.w),
                                     make_float2(oD.x, oD.y), make_float2(oD.z, oD.w) };
                    #pragma unroll
                    for (int g = 0; g < 8; ++g) {
                        ffma2(acc[g][0], dp[g], w1l);
                        ffma2(acc[g][1], dp[g], w1h);
                        ffma2(acc[g][0], op[g], w2l);
                        ffma2(acc[g][1], op[g], w2h);
                    }
                }
            }
            if (jh == 0) {
                #pragma unroll
                for (int g = 0; g < 8; ++g)
                    *(float4*)&s_lg8[g * LL + q4] =
                        make_float4(acc[g][0].x, acc[g][0].y, acc[g][1].x, acc[g][1].y);
            }
        }
        __syncthreads();
        if (jh == 1) {
            const int q4 = lk * 4;
            const int pb = (rank ^ 1) * 4;
            #pragma unroll
            for (int g = 0; g < 8; ++g) {
                float4 p = *(const float4*)&s_lg8[g * LL + q4];
                float4 c = make_float4(p.x + acc[g][0].x, p.y + acc[g][0].y,
                                       p.z + acc[g][1].x, p.w + acc[g][1].y);
                *(float4*)&s_lg8[g * LL + q4] = c;
                if (g >= pb && g < pb + 4)
                    *(float4*)&p_lgr[(g - pb) * LL + q4] = c;
            }
        }
        cluster.sync();   // CS3: logits partials exchanged

        // ---- finalize own rows: logits (+b_post), gumbel argmax, one-hot stoch ----
        {
            const int q4 = lk * 4;
            float4 bp = *(const float4*)&b_post[q4];
            #pragma unroll
            for (int ii = 0; ii < 2; ++ii) {
                int i = jh * 2 + ii;
                int g = rank * 4 + i;
                size_t bt = (size_t)(orow0 + i) * TT + t;
                float4 pa = *(const float4*)&s_lg8[g * LL + q4];
                float4 pbv = *(const float4*)&s_lgr[i * LL + q4];
                float4 lg;
                lg.x = bp.x + pa.x + pbv.x; lg.y = bp.y + pa.y + pbv.y;
                lg.z = bp.z + pa.z + pbv.z; lg.w = bp.w + pa.w + pbv.w;
                *(float4*)&out[LG_OFF + bt * LL + q4] = lg;
                float4 g4 = *(const float4*)&gumbel[((size_t)t * BB + orow0 + i) * LL + q4];
                float v0 = lg.x + g4.x, v1 = lg.y + g4.y;
                float v2 = lg.z + g4.z, v3 = lg.w + g4.w;
                float bv = v0; int bi = q4;
                if (v1 > bv) { bv = v1; bi = q4 + 1; }
                if (v2 > bv) { bv = v2; bi = q4 + 2; }
                if (v3 > bv) { bv = v3; bi = q4 + 3; }
                #pragma unroll
                for (int off = 1; off < 8; off <<= 1) {
                    float ov = __shfl_xor_sync(0xffffffffu, bv, off);
                    int   oi = __shfl_xor_sync(0xffffffffu, bi, off);
                    if (ov > bv || (ov == bv && oi < bi)) { bv = ov; bi = oi; }
                }
                float4 sv;
                sv.x = (q4 + 0 == bi) ? 1.f : 0.f;
                sv.y = (q4 + 1 == bi) ? 1.f : 0.f;
                sv.z = (q4 + 2 == bi) ? 1.f : 0.f;
                sv.w = (q4 + 3 == bi) ? 1.f : 0.f;
                *(float4*)&out[ST_OFF + bt * LL + q4] = sv;
                if ((lk & 7) == 0) s_idx[i][lk >> 3] = bi & 31;
            }
        }
        cur ^= 1;
    }
}

// ---------------- launcher ----------------
extern "C" void kernel_launch(void* const* d_in, const int* in_sizes, int n_in,
                              void* d_out, int out_size) {
    const float* obs          = (const float*)d_in[0];
    const float* action       = (const float*)d_in[1];
    const unsigned int* first = (const unsigned int*)d_in[2];
    const float* gumbel       = (const float*)d_in[3];
    const float* W_in         = (const float*)d_in[4];
    const float* b_in         = (const float*)d_in[5];
    const float* W_ih         = (const float*)d_in[6];
    const float* W_hh         = (const float*)d_in[7];
    const float* b_ih         = (const float*)d_in[8];
    const float* b_hh         = (const float*)d_in[9];
    const float* W_post       = (const float*)d_in[10];
    const float* b_post       = (const float*)d_in[11];
    float* out = (float*)d_out;
    (void)in_sizes; (void)n_in; (void)out_size;

    static int smem_set = 0;
    if (!smem_set) {
        cudaFuncSetAttribute(scan_kernel, cudaFuncAttributeMaxDynamicSharedMemorySize,
                             SMEM_FLOATS * sizeof(float));
        smem_set = 1;
    }

    prep_fuse<<<(KG * 1031 + 255) / 256, 256>>>(W_in, b_in, W_ih, b_ih);
    prep_transpose<<<(KG * RR + LL * (RR + HH) + 255) / 256, 256>>>(W_hh, W_post);
    scan_kernel<<<NCTA, 512, SMEM_FLOATS * sizeof(float)>>>(obs, action, first, gumbel,
                                                            b_hh, b_post, out);
}

// round 11
// speedup vs baseline: 1.1837x; 1.1837x over previous
#include <cuda_runtime.h>
#include <cooperative_groups.h>
#include <cstdint>

namespace cg = cooperative_groups;

// ---------------- problem dims ----------------
#define BB 512
#define TT 64
#define HH 256     // hidden / obs dim
#define AA 6       // action dim
#define RR 256     // recurrent dim
#define KG 768     // 3*RR gate dim
#define LL 1024    // latent dim
#define NCTA 128   // CTAs (64 clusters of 2); each cluster owns 8 rows, each CTA owns 4

// output layout: [deter | stoch | logits]
#define DET_OFF 0
#define ST_OFF  (BB * TT * RR)
#define LG_OFF  (BB * TT * RR + BB * TT * LL)

// ---------------- device scratch ----------------
__device__ __align__(16) float g_WcT[LL * KG];     // [c][k] fused stoch weights
__device__ __align__(16) float g_WcaT[AA * KG];    // [j][k] fused action weights
__device__ __align__(16) float g_bc[KG];           // b_ih + W_ih @ b_in
__device__ __align__(16) float g_WhhT[RR * KG];    // [j][k]
__device__ __align__(16) float g_WphT[RR * LL];    // [j][l]
__device__ __align__(16) float g_WpoT[HH * LL];    // [k][n]

// ---------------- packed fp32 helpers (FFMA2 path) ----------------
__device__ __forceinline__ void ffma2(float2& d, const float2 a, const float2 b) {
    asm("fma.rn.f32x2 %0, %1, %2, %0;"
        : "+l"(reinterpret_cast<unsigned long long&>(d))
        : "l"(reinterpret_cast<const unsigned long long&>(a)),
          "l"(reinterpret_cast<const unsigned long long&>(b)));
}

// ---------------- prep 1: fused GEMM  C[c][k] = sum_h W_in[h][c] * W_ih[k][h] ----------------
// M = 1031 (c: 1024 stoch + 6 action + 1 bias), N = 768 (k), K = 256 (h).
// 64x64 tiles, BK=16, 256 threads, 4x4 microtile.
__global__ void __launch_bounds__(256) prep_fuse(const float* __restrict__ W_in,
                                                 const float* __restrict__ b_in,
                                                 const float* __restrict__ W_ih,
                                                 const float* __restrict__ b_ih) {
    __shared__ float As[16][64 + 1];   // [kk][cc]  (A = W_in row-sliced, bias col appended)
    __shared__ float Bs[16][64 + 1];   // [kk][kn]  (B = W_ih transposed tile)
    const int tid = threadIdx.x;
    const int bk = blockIdx.x * 64;    // k base (0..704)
    const int bc = blockIdx.y * 64;    // c base (0..1024)
    const int tyc = tid >> 4;          // 0..15 -> c micro row
    const int txk = tid & 15;          // 0..15 -> k micro col

    float acc[4][4];
    #pragma unroll
    for (int i = 0; i < 4; ++i)
        #pragma unroll
        for (int j = 0; j < 4; ++j) acc[i][j] = 0.f;

    for (int k0 = 0; k0 < HH; k0 += 16) {
        // A tile: 16x64, coalesced along c.  c==1030 -> b_in, c>1030 -> 0
        #pragma unroll
        for (int i = 0; i < 4; ++i) {
            int e = tid + i * 256;
            int kk = e >> 6, cc = e & 63;
            int c = bc + cc;
            float v = 0.f;
            if (c < 1030)       v = W_in[(size_t)(k0 + kk) * 1030 + c];
            else if (c == 1030) v = b_in[k0 + kk];
            As[kk][cc] = v;
        }
        // B tile: Bs[kk][kn] = W_ih[(bk+kn)][k0+kk], 16-float segments per kn
        #pragma unroll
        for (int i = 0; i < 4; ++i) {
            int e = tid + i * 256;
            int kn = e >> 4, kk = e & 15;
            Bs[kk][kn] = W_ih[(size_t)(bk + kn) * HH + k0 + kk];
        }
        __syncthreads();
        #pragma unroll
        for (int kk = 0; kk < 16; ++kk) {
            float a[4], b[4];
            #pragma unroll
            for (int i = 0; i < 4; ++i) a[i] = As[kk][tyc * 4 + i];
            #pragma unroll
            for (int j = 0; j < 4; ++j) b[j] = Bs[kk][txk * 4 + j];
            #pragma unroll
            for (int i = 0; i < 4; ++i)
                #pragma unroll
                for (int j = 0; j < 4; ++j)
                    acc[i][j] = fmaf(a[i], b[j], acc[i][j]);
        }
        __syncthreads();
    }
    // write out, routed by c
    #pragma unroll
    for (int i = 0; i < 4; ++i) {
        int c = bc + tyc * 4 + i;
        int k = bk + txk * 4;
        if (c < LL) {
            *(float4*)&g_WcT[(size_t)c * KG + k] =
                make_float4(acc[i][0], acc[i][1], acc[i][2], acc[i][3]);
        } else if (c < 1030) {
            *(float4*)&g_WcaT[(size_t)(c - LL) * KG + k] =
                make_float4(acc[i][0], acc[i][1], acc[i][2], acc[i][3]);
        } else if (c == 1030) {
            float4 bi = *(const float4*)&b_ih[k];
            g_bc[k + 0] = acc[i][0] + bi.x;
            g_bc[k + 1] = acc[i][1] + bi.y;
            g_bc[k + 2] = acc[i][2] + bi.z;
            g_bc[k + 3] = acc[i][3] + bi.w;
        }
    }
}

// ---------------- prep 2: tiled transposes (coalesced both sides) ----------------
// z==0: W_hh [KG][RR]  -> g_WhhT [RR][KG]          (tiles 24 x 8)
// z==1: W_post [LL][RR+HH] -> g_WphT [RR][LL], g_WpoT [HH][LL]  (tiles 32 x 16)
__global__ void __launch_bounds__(256) prep_transpose(const float* __restrict__ W_hh,
                                                      const float* __restrict__ W_post) {
    __shared__ float tile[32][33];
    const int tid = threadIdx.x;
    const int tx = tid & 31;
    const int ty0 = tid >> 5;          // 0..7
    const int z = blockIdx.z;
    const int row0 = blockIdx.x * 32;  // input row base
    const int col0 = blockIdx.y * 32;  // input col base

    if (z == 0) {
        if (blockIdx.x >= 24 || blockIdx.y >= 8) return;
        #pragma unroll
        for (int r = 0; r < 4; ++r) {
            int row = ty0 + r * 8;
            tile[row][tx] = W_hh[(size_t)(row0 + row) * RR + col0 + tx];
        }
        __syncthreads();
        #pragma unroll
        for (int r = 0; r < 4; ++r) {
            int row = ty0 + r * 8;          // output row within tile (= input col)
            g_WhhT[(size_t)(col0 + row) * KG + row0 + tx] = tile[tx][row];
        }
    } else {
        #pragma unroll
        for (int r = 0; r < 4; ++r) {
            int row = ty0 + r * 8;
            tile[row][tx] = W_post[(size_t)(row0 + row) * (RR + HH) + col0 + tx];
        }
        __syncthreads();
        #pragma unroll
        for (int r = 0; r < 4; ++r) {
            int row = ty0 + r * 8;
            int m = col0 + row;             // input col = output row
            float v = tile[tx][row];
            if (m < RR) g_WphT[(size_t)m * LL + row0 + tx] = v;
            else        g_WpoT[(size_t)(m - RR) * LL + row0 + tx] = v;
        }
    }
}

// ---------------- obs GEMM (proven: 128x64, BK=16, f32x2) ----------------
__global__ void __launch_bounds__(256) obs_gemm(const float* __restrict__ obs,
                                                const float* __restrict__ b_post,
                                                float* __restrict__ outL) {
    __shared__ float2 As2[128][17];   // duplicated {a,a}
    __shared__ float  Bs[16][64];
    int tid = threadIdx.x;
    int bm = blockIdx.y * 128;
    int bn = blockIdx.x * 64;
    int ty = tid >> 4;
    int tx = tid & 15;
    float2 acc2[8][2];
    #pragma unroll
    for (int i = 0; i < 8; ++i) { acc2[i][0] = make_float2(0.f, 0.f); acc2[i][1] = make_float2(0.f, 0.f); }

    for (int k0 = 0; k0 < HH; k0 += 16) {
        #pragma unroll
        for (int i = 0; i < 2; ++i) {
            int f = tid + i * 256;
            int row = f >> 2;
            int kp = (f & 3) * 4;
            float4 v = *(const float4*)&obs[(size_t)(bm + row) * HH + k0 + kp];
            As2[row][kp + 0] = make_float2(v.x, v.x);
            As2[row][kp + 1] = make_float2(v.y, v.y);
            As2[row][kp + 2] = make_float2(v.z, v.z);
            As2[row][kp + 3] = make_float2(v.w, v.w);
        }
        #pragma unroll
        for (int i = 0; i < 4; ++i) {
            int e = tid + i * 256;
            int kk = e >> 6;
            int n = e & 63;
            Bs[kk][n] = g_WpoT[(k0 + kk) * LL + bn + n];
        }
        __syncthreads();
        #pragma unroll
        for (int kk = 0; kk < 16; ++kk) {
            float2 b0 = *(const float2*)&Bs[kk][tx * 4];
            float2 b1 = *(const float2*)&Bs[kk][tx * 4 + 2];
            #pragma unroll
            for (int i = 0; i < 8; ++i) {
                float2 a2 = As2[ty * 8 + i][kk];
                ffma2(acc2[i][0], a2, b0);
                ffma2(acc2[i][1], a2, b1);
            }
        }
        __syncthreads();
    }
    float bp0 = b_post[bn + tx * 4], bp1 = b_post[bn + tx * 4 + 1];
    float bp2 = b_post[bn + tx * 4 + 2], bp3 = b_post[bn + tx * 4 + 3];
    #pragma unroll
    for (int i = 0; i < 8; ++i) {
        int m = bm + ty * 8 + i;
        float4 v;
        v.x = acc2[i][0].x + bp0; v.y = acc2[i][0].y + bp1;
        v.z = acc2[i][1].x + bp2; v.w = acc2[i][1].y + bp3;
        *(float4*)&outL[(size_t)m * LL + bn + tx * 4] = v;
    }
}

// ---------------- cluster-2 persistent scan (round-9 proven version) ----------------
#define OFF_GI     0
#define OFF_GH8    3072
#define OFF_GHR    9216
#define OFF_DET8   12288
#define OFF_DETOWN 16384
#define OFF_LG8    18432
#define OFF_LGR    26624
#define SMEM_FLOATS 30720

__global__ void __launch_bounds__(512, 1) __cluster_dims__(2, 1, 1)
scan_kernel(const float* __restrict__ action,
            const unsigned int* __restrict__ first,
            const float* __restrict__ gumbel,       // [T][B][1024]
            const float* __restrict__ b_hh,
            float* __restrict__ out) {

    extern __shared__ float smem[];
    float* s_gi     = smem + OFF_GI;
    float* s_gh8    = smem + OFF_GH8;
    float* s_ghr    = smem + OFF_GHR;
    float* s_det8   = smem + OFF_DET8;
    float* s_detown = smem + OFF_DETOWN;
    float* s_lg8    = smem + OFF_LG8;
    float* s_lgr    = smem + OFF_LGR;
    __shared__ int   s_idx[4][32];
    __shared__ float s_act[4][AA];
    __shared__ int   s_reset[8];     // pair-global rows, first[t]

    cg::cluster_group cluster = cg::this_cluster();
    const int rank = (int)cluster.block_rank();
    float* p_ghr  = (float*)cluster.map_shared_rank(s_ghr,  rank ^ 1);
    float* p_det8 = (float*)cluster.map_shared_rank(s_det8, rank ^ 1);
    float* p_lgr  = (float*)cluster.map_shared_rank(s_lgr,  rank ^ 1);

    const int tid = threadIdx.x;
    const int jh  = tid >> 8;        // intra-CTA jj-half
    const int lk  = tid & 255;
    const int pair  = blockIdx.x >> 1;
    const int prow0 = pair * 8;
    const int orow0 = prow0 + rank * 4;      // own rows base
    const int Jbase = rank * 128;            // this CTA's j slice
    int cur = 0;

    for (int t = 0; t < TT; ++t) {
        // ---- flags (all 8 rows) + action (own rows) ----
        if (tid < 8) {
            unsigned f = first[(prow0 + tid) * TT + t];
            s_reset[tid] = (t == 0) || (f != 0u);
        }
        if (tid >= 32 && tid < 32 + 4 * AA) {
            int e = tid - 32;
            s_act[e / AA][e % AA] = action[((size_t)(orow0 + e / AA) * TT + t) * AA + (e % AA)];
        }
        __syncthreads();

        // ---- zero carries on reset (det8 slice: all 8 rows; detown: own rows) ----
        #pragma unroll
        for (int k = 0; k < 2; ++k) {
            int idx = tid + k * 512;       // 1024 items: det8 slice
            int jj = idx >> 3, g = idx & 7;
            if (s_reset[g])
                *(float2*)&s_det8[cur * 2048 + jj * 16 + 2 * g] = make_float2(0.f, 0.f);
        }
        #pragma unroll
        for (int k = 0; k < 2; ++k) {
            int idx = tid + k * 512;       // 1024 items: detown
            int r = idx >> 8, u = idx & 255;
            if (s_reset[rank * 4 + r])
                s_detown[cur * 1024 + r * 256 + u] = 0.f;
        }
        __syncthreads();

        // ---- gi for own rows (bias + action + one-hot gather) ----
        for (int item = tid; item < 4 * 192; item += 512) {
            int r = item / 192;
            int q = (item % 192) * 4;
            float4 a4 = *(const float4*)&g_bc[q];
            #pragma unroll
            for (int j = 0; j < AA; ++j) {
                float av = s_act[r][j];
                float4 w = *(const float4*)&g_WcaT[j * KG + q];
                a4.x = fmaf(av, w.x, a4.x); a4.y = fmaf(av, w.y, a4.y);
                a4.z = fmaf(av, w.z, a4.z); a4.w = fmaf(av, w.w, a4.w);
            }
            if (!s_reset[rank * 4 + r]) {
                #pragma unroll 8
                for (int g = 0; g < 32; ++g) {
                    int c = (g << 5) + s_idx[r][g];
                    float4 w = *(const float4*)&g_WcT[c * KG + q];
                    a4.x += w.x; a4.y += w.y; a4.z += w.z; a4.w += w.w;
                }
            }
            *(float4*)&s_gi[r * KG + q] = a4;
        }

        // ---- phase 1: gh partial over my j-slice (8-deep weight prefetch) ----
        float2 gh[8][2];
        if (lk < 192) {
            const int q4 = lk * 4;
            if (rank == 0 && jh == 0) {
                float4 bh = *(const float4*)&b_hh[q4];
                #pragma unroll
                for (int g = 0; g < 8; ++g) {
                    gh[g][0] = make_float2(bh.x, bh.y);
                    gh[g][1] = make_float2(bh.z, bh.w);
                }
            } else {
                #pragma unroll
                for (int g = 0; g < 8; ++g) {
                    gh[g][0] = make_float2(0.f, 0.f);
                    gh[g][1] = make_float2(0.f, 0.f);
                }
            }
            const float4* wp  = (const float4*)&g_WhhT[(size_t)(Jbase + jh * 64) * KG + q4];
            const size_t  WS  = KG / 4;
            const float4* db4 = (const float4*)(s_det8 + cur * 2048 + (jh * 64) * 16);
            float4 wb8[8];
            #pragma unroll
            for (int p = 0; p < 8; ++p) wb8[p] = wp[(size_t)p * WS];
            #pragma unroll 1
            for (int base = 0; base < 64; base += 8) {
                #pragma unroll
                for (int p = 0; p < 8; ++p) {
                    float4 w = wb8[p];
                    int nj = base + 8 + p; nj = (nj < 64) ? nj : 63;
                    wb8[p] = wp[(size_t)nj * WS];
                    const float4* dq = db4 + (size_t)(base + p) * 4;
                    float4 dA = dq[0], dB = dq[1], dC = dq[2], dD = dq[3];
                    float2 wl = make_float2(w.x, w.y), wh2 = make_float2(w.z, w.w);
                    float2 dp[8] = { make_float2(dA.x, dA.y), make_float2(dA.z, dA.w),
                                     make_float2(dB.x, dB.y), make_float2(dB.z, dB.w),
                                     make_float2(dC.x, dC.y), make_float2(dC.z, dC.w),
                                     make_float2(dD.x, dD.y), make_float2(dD.z, dD.w) };
                    #pragma unroll
                    for (int g = 0; g < 8; ++g) {
                        ffma2(gh[g][0], dp[g], wl);
                        ffma2(gh[g][1], dp[g], wh2);
                    }
                }
            }
            if (jh == 0) {
                #pragma unroll
                for (int g = 0; g < 8; ++g)
                    *(float4*)&s_gh8[g * KG + q4] =
                        make_float4(gh[g][0].x, gh[g][0].y, gh[g][1].x, gh[g][1].y);
            }
        }
        __syncthreads();
        if (jh == 1 && lk < 192) {   // combine halves; push peer rows to peer's s_ghr
            const int q4 = lk * 4;
            const int pb = (rank ^ 1) * 4;
            #pragma unroll
            for (int g = 0; g < 8; ++g) {
                float4 p = *(const float4*)&s_gh8[g * KG + q4];
                float4 c = make_float4(p.x + gh[g][0].x, p.y + gh[g][0].y,
                                       p.z + gh[g][1].x, p.w + gh[g][1].y);
                *(float4*)&s_gh8[g * KG + q4] = c;
                if (g >= pb && g < pb + 4)
                    *(float4*)&p_ghr[(g - pb) * KG + q4] = c;
            }
        }
        cluster.sync();   // CS1: gh partials exchanged

        // ---- GRU for own rows + det distribution (true h everywhere) ----
        {
            const int u = lk;
            #pragma unroll
            for (int ii = 0; ii < 2; ++ii) {
                int i = jh * 2 + ii;          // own-local row
                int g = rank * 4 + i;         // pair-global row
                float ir = s_gi[i * KG + u];
                float hr = s_gh8[g * KG + u]       + s_ghr[i * KG + u];
                float iz = s_gi[i * KG + u + 256];
                float hz = s_gh8[g * KG + u + 256] + s_ghr[i * KG + u + 256];
                float in_ = s_gi[i * KG + u + 512];
                float hn = s_gh8[g * KG + u + 512] + s_ghr[i * KG + u + 512];
                float rg = 1.f / (1.f + expf(-(ir + hr)));
                float z  = 1.f / (1.f + expf(-(iz + hz)));
                float n  = tanhf(fmaf(rg, hn, in_));
                float dp = s_detown[cur * 1024 + i * 256 + u];
                float h  = (1.f - z) * n + z * dp;
                s_detown[(cur ^ 1) * 1024 + i * 256 + u] = h;
                float2 hh = make_float2(h, h);
                int jloc = u & 127;
                if ((u >> 7) == rank)
                    *(float2*)&s_det8[(cur ^ 1) * 2048 + jloc * 16 + 2 * g] = hh;
                else
                    *(float2*)&p_det8[(cur ^ 1) * 2048 + jloc * 16 + 2 * g] = hh;
                out[DET_OFF + ((size_t)(orow0 + i) * TT + t) * RR + u] = h;
            }
        }
        cluster.sync();   // CS2: new det slices exchanged

        // ---- phase 2: logits partial over my j-slice (8-deep weight prefetch) ----
        float2 acc[8][2];
        {
            const int q4 = lk * 4;
            #pragma unroll
            for (int g = 0; g < 8; ++g) {
                acc[g][0] = make_float2(0.f, 0.f);
                acc[g][1] = make_float2(0.f, 0.f);
            }
            const float4* wp  = (const float4*)&g_WphT[(size_t)(Jbase + jh * 64) * LL + q4];
            const size_t  WS  = LL / 4;
            const float4* db4 = (const float4*)(s_det8 + (cur ^ 1) * 2048 + (jh * 64) * 16);
            float4 wb8[8];
            #pragma unroll
            for (int p = 0; p < 8; ++p) wb8[p] = wp[(size_t)p * WS];
            #pragma unroll 1
            for (int base = 0; base < 64; base += 8) {
                #pragma unroll
                for (int p = 0; p < 8; ++p) {
                    float4 w = wb8[p];
                    int nj = base + 8 + p; nj = (nj < 64) ? nj : 63;
                    wb8[p] = wp[(size_t)nj * WS];
                    const float4* dq = db4 + (size_t)(base + p) * 4;
                    float4 dA = dq[0], dB = dq[1], dC = dq[2], dD = dq[3];
                    float2 wl = make_float2(w.x, w.y), wh2 = make_float2(w.z, w.w);
                    float2 dp[8] = { make_float2(dA.x, dA.y), make_float2(dA.z, dA.w),
                                     make_float2(dB.x, dB.y), make_float2(dB.z, dB.w),
                                     make_float2(dC.x, dC.y), make_float2(dC.z, dC.w),
                                     make_float2(dD.x, dD.y), make_float2(dD.z, dD.w) };
                    #pragma unroll
                    for (int g = 0; g < 8; ++g) {
                        ffma2(acc[g][0], dp[g], wl);
                        ffma2(acc[g][1], dp[g], wh2);
                    }
                }
            }
            if (jh == 0) {
                #pragma unroll
                for (int g = 0; g < 8; ++g)
                    *(float4*)&s_lg8[g * LL + q4] =
                        make_float4(acc[g][0].x, acc[g][0].y, acc[g][1].x, acc[g][1].y);
            }
        }
        __syncthreads();
        if (jh == 1) {
            const int q4 = lk * 4;
            const int pb = (rank ^ 1) * 4;
            #pragma unroll
            for (int g = 0; g < 8; ++g) {
                float4 p = *(const float4*)&s_lg8[g * LL + q4];
                float4 c = make_float4(p.x + acc[g][0].x, p.y + acc[g][0].y,
                                       p.z + acc[g][1].x, p.w + acc[g][1].y);
                *(float4*)&s_lg8[g * LL + q4] = c;
                if (g >= pb && g < pb + 4)
                    *(float4*)&p_lgr[(g - pb) * LL + q4] = c;
            }
        }
        cluster.sync();   // CS3: logits partials exchanged

        // ---- finalize own rows: logits, gumbel argmax, one-hot stoch ----
        {
            const int q4 = lk * 4;
            #pragma unroll
            for (int ii = 0; ii < 2; ++ii) {
                int i = jh * 2 + ii;
                int g = rank * 4 + i;
                size_t bt = (size_t)(orow0 + i) * TT + t;
                float4 ob = *(const float4*)&out[LG_OFF + bt * LL + q4];  // obs part + b_post
                float4 pa = *(const float4*)&s_lg8[g * LL + q4];
                float4 pbv = *(const float4*)&s_lgr[i * LL + q4];
                float4 lg;
                lg.x = ob.x + pa.x + pbv.x; lg.y = ob.y + pa.y + pbv.y;
                lg.z = ob.z + pa.z + pbv.z; lg.w = ob.w + pa.w + pbv.w;
                *(float4*)&out[LG_OFF + bt * LL + q4] = lg;
                float4 g4 = *(const float4*)&gumbel[((size_t)t * BB + orow0 + i) * LL + q4];
                float v0 = lg.x + g4.x, v1 = lg.y + g4.y;
                float v2 = lg.z + g4.z, v3 = lg.w + g4.w;
                float bv = v0; int bi = q4;
                if (v1 > bv) { bv = v1; bi = q4 + 1; }
                if (v2 > bv) { bv = v2; bi = q4 + 2; }
                if (v3 > bv) { bv = v3; bi = q4 + 3; }
                #pragma unroll
                for (int off = 1; off < 8; off <<= 1) {
                    float ov = __shfl_xor_sync(0xffffffffu, bv, off);
                    int   oi = __shfl_xor_sync(0xffffffffu, bi, off);
                    if (ov > bv || (ov == bv && oi < bi)) { bv = ov; bi = oi; }
                }
                float4 sv;
                sv.x = (q4 + 0 == bi) ? 1.f : 0.f;
                sv.y = (q4 + 1 == bi) ? 1.f : 0.f;
                sv.z = (q4 + 2 == bi) ? 1.f : 0.f;
                sv.w = (q4 + 3 == bi) ? 1.f : 0.f;
                *(float4*)&out[ST_OFF + bt * LL + q4] = sv;
                if ((lk & 7) == 0) s_idx[i][lk >> 3] = bi & 31;
            }
        }
        cur ^= 1;
    }
}

// ---------------- launcher ----------------
extern "C" void kernel_launch(void* const* d_in, const int* in_sizes, int n_in,
                              void* d_out, int out_size) {
    const float* obs          = (const float*)d_in[0];
    const float* action       = (const float*)d_in[1];
    const unsigned int* first = (const unsigned int*)d_in[2];
    const float* gumbel       = (const float*)d_in[3];
    const float* W_in         = (const float*)d_in[4];
    const float* b_in         = (const float*)d_in[5];
    const float* W_ih         = (const float*)d_in[6];
    const float* W_hh         = (const float*)d_in[7];
    const float* b_ih         = (const float*)d_in[8];
    const float* b_hh         = (const float*)d_in[9];
    const float* W_post       = (const float*)d_in[10];
    const float* b_post       = (const float*)d_in[11];
    float* out = (float*)d_out;
    (void)in_sizes; (void)n_in; (void)out_size;

    static int smem_set = 0;
    if (!smem_set) {
        cudaFuncSetAttribute(scan_kernel, cudaFuncAttributeMaxDynamicSharedMemorySize,
                             SMEM_FLOATS * sizeof(float));
        smem_set = 1;
    }

    prep_fuse<<<dim3(KG / 64, 17), 256>>>(W_in, b_in, W_ih, b_ih);
    prep_transpose<<<dim3(32, 16, 2), 256>>>(W_hh, W_post);
    dim3 ggrid(LL / 64, (BB * TT) / 128);
    obs_gemm<<<ggrid, 256>>>(obs, b_post, out + LG_OFF);
    scan_kernel<<<NCTA, 512, SMEM_FLOATS * sizeof(float)>>>(action, first, gumbel, b_hh, out);
}